// round 1
// baseline (speedup 1.0000x reference)
#include <cuda_runtime.h>
#include <cuda_bf16.h>

#define B_    8
#define N_    8192
#define M_    2048
#define C1_   128
#define C2_   256
#define H1_   256   // MLP[0]
#define H2_   128   // MLP[1]
#define CIN_  (C2_ + C1_)   // 384
#define BNPTS (B_ * N_)     // 65536

// ---------------- scratch (static device globals; no runtime alloc) ----------
__device__ int   g_idx[BNPTS * 3];
__device__ float g_w[BNPTS * 3];
__device__ float g_x[BNPTS * CIN_];   // concat(interp, points1)  ~100.7 MB
__device__ float g_h[BNPTS * H1_];    // hidden after layer 1      ~67 MB

// ---------------- kernel 1: three_nn ----------------------------------------
// grid: (N_/256, B_), block 256. SMEM: SoA xyz2 for one batch + |p|^2.
__global__ void knn3_kernel(const float* __restrict__ xyz1,
                            const float* __restrict__ xyz2) {
    __shared__ float sx[M_], sy[M_], sz[M_], sq[M_];
    const int b = blockIdx.y;
    const float* p2 = xyz2 + (size_t)b * M_ * 3;
    for (int j = threadIdx.x; j < M_; j += blockDim.x) {
        float x = p2[j * 3 + 0], y = p2[j * 3 + 1], z = p2[j * 3 + 2];
        sx[j] = x; sy[j] = y; sz[j] = z;
        sq[j] = x * x + y * y + z * z;
    }
    __syncthreads();

    const int n = blockIdx.x * blockDim.x + threadIdx.x;
    const int p = b * N_ + n;
    const float* q = xyz1 + (size_t)p * 3;
    const float qx = q[0], qy = q[1], qz = q[2];
    const float qx2 = 2.0f * qx, qy2 = 2.0f * qy, qz2 = 2.0f * qz;
    const float sq1 = qx * qx + qy * qy + qz * qz;

    float k0 = 3.4e38f, k1 = 3.4e38f, k2 = 3.4e38f;
    int   i0 = 0, i1 = 0, i2 = 0;

    #pragma unroll 4
    for (int j = 0; j < M_; j++) {
        // key = |p2|^2 - 2 <q, p2>   (same expansion as reference, minus |q|^2)
        float key = sq[j];
        key = fmaf(-qx2, sx[j], key);
        key = fmaf(-qy2, sy[j], key);
        key = fmaf(-qz2, sz[j], key);
        if (key < k2) {
            if (key < k1) {
                k2 = k1; i2 = i1;
                if (key < k0) { k1 = k0; i1 = i0; k0 = key; i0 = j; }
                else          { k1 = key; i1 = j; }
            } else { k2 = key; i2 = j; }
        }
    }

    float d0 = fmaxf(k0 + sq1, 1e-10f);
    float d1 = fmaxf(k1 + sq1, 1e-10f);
    float d2 = fmaxf(k2 + sq1, 1e-10f);
    float w0 = 1.0f / d0, w1 = 1.0f / d1, w2 = 1.0f / d2;
    float inv = 1.0f / (w0 + w1 + w2);
    g_idx[p * 3 + 0] = i0; g_idx[p * 3 + 1] = i1; g_idx[p * 3 + 2] = i2;
    g_w[p * 3 + 0] = w0 * inv; g_w[p * 3 + 1] = w1 * inv; g_w[p * 3 + 2] = w2 * inv;
}

// ---------------- kernel 2: interpolate + concat -----------------------------
// warp per point; float4 gather of 3 rows of points2, blend, copy points1.
__global__ void interp_kernel(const float* __restrict__ points2,
                              const float* __restrict__ points1) {
    const int warp = (blockIdx.x * blockDim.x + threadIdx.x) >> 5;
    const int lane = threadIdx.x & 31;
    if (warp >= BNPTS) return;
    const int b = warp >> 13;  // / N_
    const int i0 = g_idx[warp * 3 + 0];
    const int i1 = g_idx[warp * 3 + 1];
    const int i2 = g_idx[warp * 3 + 2];
    const float w0 = g_w[warp * 3 + 0];
    const float w1 = g_w[warp * 3 + 1];
    const float w2 = g_w[warp * 3 + 2];

    const float4* base = (const float4*)(points2 + (size_t)b * M_ * C2_);
    float4* xr = (float4*)(g_x + (size_t)warp * CIN_);

    #pragma unroll
    for (int c = lane; c < C2_ / 4; c += 32) {
        float4 a = base[(size_t)i0 * (C2_ / 4) + c];
        float4 bb = base[(size_t)i1 * (C2_ / 4) + c];
        float4 cc = base[(size_t)i2 * (C2_ / 4) + c];
        float4 r;
        r.x = w0 * a.x + w1 * bb.x + w2 * cc.x;
        r.y = w0 * a.y + w1 * bb.y + w2 * cc.y;
        r.z = w0 * a.z + w1 * bb.z + w2 * cc.z;
        r.w = w0 * a.w + w1 * bb.w + w2 * cc.w;
        xr[c] = r;
    }
    const float4* p1 = (const float4*)(points1 + (size_t)warp * C1_);
    xr[C2_ / 4 + lane] = p1[lane];            // 32 float4 = 128 floats
}

// ---------------- kernel 3: SGEMM + bias + relu ------------------------------
// C[M,N] = relu(A[M,K] @ B[K,N] + bias). BM=BN=128, BK=8, 256 thr, 8x8/thread.
__global__ __launch_bounds__(256, 2)
void sgemm_bias_relu(const float* __restrict__ A, const float* __restrict__ Bm,
                     const float* __restrict__ bias, float* __restrict__ C,
                     int M, int N, int K) {
    __shared__ float As[8][128];
    __shared__ float Bs[8][128];

    const int tid = threadIdx.x;
    const int tx = tid % 16;          // N direction
    const int ty = tid / 16;          // M direction
    const int arow = tid >> 1;        // 0..127
    const int acol = (tid & 1) * 4;   // 0 or 4
    const int brow = tid >> 5;        // 0..7
    const int bcol = (tid & 31) * 4;  // 0..124

    const float* Ab = A + (size_t)(blockIdx.y * 128) * K;
    const float* Bb = Bm + blockIdx.x * 128;

    float acc[8][8];
    #pragma unroll
    for (int i = 0; i < 8; i++)
        #pragma unroll
        for (int j = 0; j < 8; j++) acc[i][j] = 0.0f;

    for (int k0 = 0; k0 < K; k0 += 8) {
        float4 av = *(const float4*)(Ab + (size_t)arow * K + k0 + acol);
        As[acol + 0][arow] = av.x;
        As[acol + 1][arow] = av.y;
        As[acol + 2][arow] = av.z;
        As[acol + 3][arow] = av.w;
        float4 bv = *(const float4*)(Bb + (size_t)(k0 + brow) * N + bcol);
        *(float4*)&Bs[brow][bcol] = bv;
        __syncthreads();

        #pragma unroll
        for (int k = 0; k < 8; k++) {
            float ar[8], br[8];
            *(float4*)&ar[0] = *(const float4*)&As[k][ty * 8 + 0];
            *(float4*)&ar[4] = *(const float4*)&As[k][ty * 8 + 4];
            *(float4*)&br[0] = *(const float4*)&Bs[k][tx * 8 + 0];
            *(float4*)&br[4] = *(const float4*)&Bs[k][tx * 8 + 4];
            #pragma unroll
            for (int i = 0; i < 8; i++)
                #pragma unroll
                for (int j = 0; j < 8; j++)
                    acc[i][j] = fmaf(ar[i], br[j], acc[i][j]);
        }
        __syncthreads();
    }

    const int crow = blockIdx.y * 128 + ty * 8;
    const int ccol = blockIdx.x * 128 + tx * 8;
    #pragma unroll
    for (int j = 0; j < 8; j++) {
        float bj = bias[ccol + j];
        #pragma unroll
        for (int i = 0; i < 8; i++) {
            float v = acc[i][j] + bj;
            C[(size_t)(crow + i) * N + ccol + j] = v > 0.0f ? v : 0.0f;
        }
    }
}

// ---------------- launch ------------------------------------------------------
extern "C" void kernel_launch(void* const* d_in, const int* in_sizes, int n_in,
                              void* d_out, int out_size) {
    const float* xyz1    = (const float*)d_in[0];
    const float* xyz2    = (const float*)d_in[1];
    const float* points1 = (const float*)d_in[2];
    const float* points2 = (const float*)d_in[3];
    const float* W1      = (const float*)d_in[4];
    const float* b1      = (const float*)d_in[5];
    const float* W2      = (const float*)d_in[6];
    const float* b2      = (const float*)d_in[7];
    float* out = (float*)d_out;

    float *gx, *gh;
    cudaGetSymbolAddress((void**)&gx, g_x);
    cudaGetSymbolAddress((void**)&gh, g_h);

    // 1) three_nn
    dim3 g1(N_ / 256, B_);
    knn3_kernel<<<g1, 256>>>(xyz1, xyz2);

    // 2) interpolate + concat (warp per point, 8 warps/block)
    interp_kernel<<<BNPTS / 8, 256>>>(points2, points1);

    // 3) layer 1: [65536,384] @ [384,256] -> g_h
    dim3 g3(H1_ / 128, BNPTS / 128);
    sgemm_bias_relu<<<g3, 256>>>(gx, W1, b1, gh, BNPTS, H1_, CIN_);

    // 4) layer 2: [65536,256] @ [256,128] -> out
    dim3 g4(H2_ / 128, BNPTS / 128);
    sgemm_bias_relu<<<g4, 256>>>(gh, W2, b2, out, BNPTS, H2_, H1_);
}

// round 4
// speedup vs baseline: 1.0238x; 1.0238x over previous
#include <cuda_runtime.h>
#include <cstdint>

#define B_    8
#define N_    8192
#define M_    2048
#define C1_   128
#define C2_   256
#define H1_   256
#define H2_   128
#define CIN_  (C2_ + C1_)   // 384
#define BNPTS (B_ * N_)     // 65536

// ---------------- scratch ----------------------------------------------------
__device__ int   g_idx[BNPTS * 3];
__device__ float g_w[BNPTS * 3];
__device__ float g_x[(size_t)BNPTS * CIN_];   // concat(interp, points1)
__device__ float g_h[(size_t)BNPTS * H1_];    // hidden after layer 1

__device__ __forceinline__ uint32_t rna_tf32(float f) {
    uint32_t r;
    asm("cvt.rna.tf32.f32 %0, %1;" : "=r"(r) : "f"(f));
    return r;
}

// ---------------- kernel 1: three_nn -----------------------------------------
__global__ void knn3_kernel(const float* __restrict__ xyz1,
                            const float* __restrict__ xyz2) {
    __shared__ float4 s2[M_];
    const int b = blockIdx.y;
    const float* p2 = xyz2 + (size_t)b * M_ * 3;
    for (int j = threadIdx.x; j < M_; j += blockDim.x) {
        float x = p2[j * 3 + 0], y = p2[j * 3 + 1], z = p2[j * 3 + 2];
        s2[j] = make_float4(x, y, z, x * x + y * y + z * z);
    }
    __syncthreads();

    const int n = blockIdx.x * blockDim.x + threadIdx.x;
    const int p = b * N_ + n;
    const float* q = xyz1 + (size_t)p * 3;
    const float qx = q[0], qy = q[1], qz = q[2];
    const float qx2 = 2.0f * qx, qy2 = 2.0f * qy, qz2 = 2.0f * qz;
    const float sq1 = qx * qx + qy * qy + qz * qz;

    float k0 = 3.4e38f, k1 = 3.4e38f, k2 = 3.4e38f;
    int   i0 = 0, i1 = 0, i2 = 0;

    #pragma unroll 8
    for (int j = 0; j < M_; j++) {
        float4 v = s2[j];
        float key = v.w;
        key = fmaf(-qx2, v.x, key);
        key = fmaf(-qy2, v.y, key);
        key = fmaf(-qz2, v.z, key);
        if (key < k2) {
            if (key < k1) {
                k2 = k1; i2 = i1;
                if (key < k0) { k1 = k0; i1 = i0; k0 = key; i0 = j; }
                else          { k1 = key; i1 = j; }
            } else { k2 = key; i2 = j; }
        }
    }

    float d0 = fmaxf(k0 + sq1, 1e-10f);
    float d1 = fmaxf(k1 + sq1, 1e-10f);
    float d2 = fmaxf(k2 + sq1, 1e-10f);
    float w0 = 1.0f / d0, w1 = 1.0f / d1, w2 = 1.0f / d2;
    float inv = 1.0f / (w0 + w1 + w2);
    g_idx[p * 3 + 0] = i0; g_idx[p * 3 + 1] = i1; g_idx[p * 3 + 2] = i2;
    g_w[p * 3 + 0] = w0 * inv; g_w[p * 3 + 1] = w1 * inv; g_w[p * 3 + 2] = w2 * inv;
}

// ---------------- kernel 2: interpolate + concat -----------------------------
__global__ void interp_kernel(const float* __restrict__ points2,
                              const float* __restrict__ points1) {
    const int warp = (blockIdx.x * blockDim.x + threadIdx.x) >> 5;
    const int lane = threadIdx.x & 31;
    if (warp >= BNPTS) return;
    const int b = warp >> 13;
    const int i0 = g_idx[warp * 3 + 0];
    const int i1 = g_idx[warp * 3 + 1];
    const int i2 = g_idx[warp * 3 + 2];
    const float w0 = g_w[warp * 3 + 0];
    const float w1 = g_w[warp * 3 + 1];
    const float w2 = g_w[warp * 3 + 2];

    const float4* base = (const float4*)(points2 + (size_t)b * M_ * C2_);
    float4* xr = (float4*)(g_x + (size_t)warp * CIN_);

    #pragma unroll
    for (int c = lane; c < C2_ / 4; c += 32) {
        float4 a = base[(size_t)i0 * (C2_ / 4) + c];
        float4 bb = base[(size_t)i1 * (C2_ / 4) + c];
        float4 cc = base[(size_t)i2 * (C2_ / 4) + c];
        float4 r;
        r.x = w0 * a.x + w1 * bb.x + w2 * cc.x;
        r.y = w0 * a.y + w1 * bb.y + w2 * cc.y;
        r.z = w0 * a.z + w1 * bb.z + w2 * cc.z;
        r.w = w0 * a.w + w1 * bb.w + w2 * cc.w;
        xr[c] = r;
    }
    const float4* p1 = (const float4*)(points1 + (size_t)warp * C1_);
    xr[C2_ / 4 + lane] = p1[lane];
}

// ---------------- kernel 3: TF32 mma.sync GEMM + bias + relu -----------------
// C[M,Ncols] = relu(A[M,KDIM] @ W[KDIM,Ncols] + bias)
// Tile 128x128xBK32. 8 warps = 2(M) x 4(N); warp tile 64x32 = 4x4 m16n8k8 frags.
// SMEM holds chunks pre-permuted into fragment order:
//  A: per (m16 tile gmt, kstep): lane -> float4 {A[r][c],A[r+8][c],A[r][c+4],A[r+8][c+4]}
//     with r = gmt*16 + lane/4, c = kstep*8 + lane%4
//  B: per (n8 tile gnt, kstep): lane -> float2 {W[k][n], W[k+4][n]}
//     with k = kstep*8 + lane%4, n = gnt*8 + lane/4

__device__ __forceinline__ void mma_tf32(float* c, const uint32_t* a,
                                         const uint32_t* b) {
    asm volatile(
        "mma.sync.aligned.m16n8k8.row.col.f32.tf32.tf32.f32 "
        "{%0,%1,%2,%3}, {%4,%5,%6,%7}, {%8,%9}, {%0,%1,%2,%3};"
        : "+f"(c[0]), "+f"(c[1]), "+f"(c[2]), "+f"(c[3])
        : "r"(a[0]), "r"(a[1]), "r"(a[2]), "r"(a[3]), "r"(b[0]), "r"(b[1]));
}

template<int KDIM>
__global__ __launch_bounds__(256, 1)
void mma_gemm(const float* __restrict__ A, const float* __restrict__ W,
              const float* __restrict__ bias, float* __restrict__ C,
              int Ncols) {
    extern __shared__ float smem[];
    float* sA = smem;          // 2 buffers x 4096 floats (128x32)
    float* sB = smem + 8192;   // 2 buffers x 4096 floats (32x128)
    constexpr int NC = KDIM / 32;

    const int tid  = threadIdx.x;
    const int wid  = tid >> 5, lane = tid & 31;
    const int wm   = wid >> 2, wn = wid & 3;
    const int m0   = blockIdx.y * 128;
    const int n0   = blockIdx.x * 128;
    const float* Ab = A + (size_t)m0 * KDIM;

    float acc[4][4][4];
    #pragma unroll
    for (int i = 0; i < 4; i++)
        #pragma unroll
        for (int j = 0; j < 4; j++)
            #pragma unroll
            for (int e = 0; e < 4; e++) acc[i][j][e] = 0.0f;

    uint32_t stA[16], stB[16];

    // ---- staging helpers (rounded to tf32 at load) ----
    auto ldg_chunk = [&](int c) {
        #pragma unroll
        for (int i = 0; i < 4; i++) {              // A: 128x32, 1024 float4
            int f = tid + i * 256;
            int r = f >> 3, f4 = f & 7;
            float4 v = *(const float4*)(Ab + (size_t)r * KDIM + c * 32 + f4 * 4);
            stA[i*4+0] = rna_tf32(v.x); stA[i*4+1] = rna_tf32(v.y);
            stA[i*4+2] = rna_tf32(v.z); stA[i*4+3] = rna_tf32(v.w);
        }
        #pragma unroll
        for (int i = 0; i < 4; i++) {              // B: 32x128, 1024 float4
            int f = tid + i * 256;
            int k = f >> 5, f4 = f & 31;
            float4 v = *(const float4*)(W + (size_t)(c * 32 + k) * Ncols + n0 + f4 * 4);
            stB[i*4+0] = rna_tf32(v.x); stB[i*4+1] = rna_tf32(v.y);
            stB[i*4+2] = rna_tf32(v.z); stB[i*4+3] = rna_tf32(v.w);
        }
    };
    auto sts_chunk = [&](int buf) {
        uint32_t* dA = (uint32_t*)(sA + buf * 4096);
        uint32_t* dB = (uint32_t*)(sB + buf * 4096);
        #pragma unroll
        for (int i = 0; i < 4; i++) {
            int f = tid + i * 256;
            int r = f >> 3, f4 = f & 7;
            int mt = r >> 4, rr = r & 15;
            int half = rr >> 3, lrow = rr & 7;
            int ks = f4 >> 1, ch = f4 & 1;
            int base = ((mt * 4 + ks) * 32 + lrow * 4) * 4 + half + 2 * ch;
            #pragma unroll
            for (int e = 0; e < 4; e++) dA[base + e * 4] = stA[i*4+e];
        }
        #pragma unroll
        for (int i = 0; i < 4; i++) {
            int f = tid + i * 256;
            int k = f >> 5, f4 = f & 31;
            int nt = f4 >> 1, nh = f4 & 1;
            int ks = k >> 3, kk = k & 7;
            int kh = kk >> 2, kl = kk & 3;
            int base = ((nt * 4 + ks) * 32 + nh * 16 + kl) * 2 + kh;
            #pragma unroll
            for (int e = 0; e < 4; e++) dB[base + e * 8] = stB[i*4+e];
        }
    };

    ldg_chunk(0);
    sts_chunk(0);
    __syncthreads();

    #pragma unroll 1
    for (int c = 0; c < NC; c++) {
        if (c + 1 < NC) ldg_chunk(c + 1);
        const int buf = c & 1;
        const float4* a4 = (const float4*)(sA + buf * 4096);
        const float2* b2 = (const float2*)(sB + buf * 4096);
        #pragma unroll
        for (int ks = 0; ks < 4; ks++) {
            uint32_t af[4][4], bf[4][2];
            #pragma unroll
            for (int mt = 0; mt < 4; mt++) {
                float4 v = a4[(((wm * 4 + mt) * 4 + ks) * 32) + lane];
                af[mt][0] = __float_as_uint(v.x); af[mt][1] = __float_as_uint(v.y);
                af[mt][2] = __float_as_uint(v.z); af[mt][3] = __float_as_uint(v.w);
            }
            #pragma unroll
            for (int nt = 0; nt < 4; nt++) {
                float2 v = b2[(((wn * 4 + nt) * 4 + ks) * 32) + lane];
                bf[nt][0] = __float_as_uint(v.x); bf[nt][1] = __float_as_uint(v.y);
            }
            #pragma unroll
            for (int mt = 0; mt < 4; mt++)
                #pragma unroll
                for (int nt = 0; nt < 4; nt++)
                    mma_tf32(acc[mt][nt], af[mt], bf[nt]);
        }
        if (c + 1 < NC) sts_chunk((c + 1) & 1);
        __syncthreads();
    }

    // ---- epilogue: bias + relu, direct float2 stores ----
    #pragma unroll
    for (int nt = 0; nt < 4; nt++) {
        const int colb = n0 + wn * 32 + nt * 8 + (lane & 3) * 2;
        float2 bv = *(const float2*)(bias + colb);
        #pragma unroll
        for (int mt = 0; mt < 4; mt++) {
            const int row0 = m0 + wm * 64 + mt * 16 + (lane >> 2);
            float v0 = fmaxf(acc[mt][nt][0] + bv.x, 0.0f);
            float v1 = fmaxf(acc[mt][nt][1] + bv.y, 0.0f);
            float v2 = fmaxf(acc[mt][nt][2] + bv.x, 0.0f);
            float v3 = fmaxf(acc[mt][nt][3] + bv.y, 0.0f);
            *(float2*)(C + (size_t)row0 * Ncols + colb)       = make_float2(v0, v1);
            *(float2*)(C + (size_t)(row0 + 8) * Ncols + colb) = make_float2(v2, v3);
        }
    }
}

// ---------------- launch ------------------------------------------------------
extern "C" void kernel_launch(void* const* d_in, const int* in_sizes, int n_in,
                              void* d_out, int out_size) {
    const float* xyz1    = (const float*)d_in[0];
    const float* xyz2    = (const float*)d_in[1];
    const float* points1 = (const float*)d_in[2];
    const float* points2 = (const float*)d_in[3];
    const float* W1      = (const float*)d_in[4];
    const float* b1      = (const float*)d_in[5];
    const float* W2      = (const float*)d_in[6];
    const float* b2      = (const float*)d_in[7];
    float* out = (float*)d_out;

    float *gx, *gh;
    cudaGetSymbolAddress((void**)&gx, g_x);
    cudaGetSymbolAddress((void**)&gh, g_h);

    const int smem = 2 * (4096 + 4096) * 4;   // 65536 bytes
    cudaFuncSetAttribute(mma_gemm<CIN_>,
                         cudaFuncAttributeMaxDynamicSharedMemorySize, smem);
    cudaFuncSetAttribute(mma_gemm<H1_>,
                         cudaFuncAttributeMaxDynamicSharedMemorySize, smem);

    // 1) three_nn
    dim3 g1(N_ / 256, B_);
    knn3_kernel<<<g1, 256>>>(xyz1, xyz2);

    // 2) interpolate + concat
    interp_kernel<<<BNPTS / 8, 256>>>(points2, points1);

    // 3) layer 1: relu(g_x[65536,384] @ W1[384,256] + b1) -> g_h
    dim3 g3(H1_ / 128, BNPTS / 128);
    mma_gemm<CIN_><<<g3, 256, smem>>>(gx, W1, b1, gh, H1_);

    // 4) layer 2: relu(g_h[65536,256] @ W2[256,128] + b2) -> out
    dim3 g4(H2_ / 128, BNPTS / 128);
    mma_gemm<H1_><<<g4, 256, smem>>>(gh, W2, b2, out, H2_);
}

// round 5
// speedup vs baseline: 2.2600x; 2.2075x over previous
#include <cuda_runtime.h>
#include <cstdint>

#define B_    8
#define N_    8192
#define M_    2048
#define C1_   128
#define C2_   256
#define H1_   256
#define H2_   128
#define CIN_  (C2_ + C1_)   // 384
#define BNPTS (B_ * N_)     // 65536

// ---------------- scratch ----------------------------------------------------
__device__ int   g_idx[BNPTS * 3];
__device__ float g_w[BNPTS * 3];
__device__ float g_x[(size_t)BNPTS * CIN_];   // tf32-rounded concat(interp, points1)
__device__ float g_h[(size_t)BNPTS * H1_];    // tf32-rounded hidden
__device__ float g_W1r[CIN_ * H1_];           // tf32-rounded W1 (row-major)
__device__ float g_W2r[H1_ * H2_];            // tf32-rounded W2

__device__ __forceinline__ float rna_tf32(float f) {
    uint32_t r;
    asm("cvt.rna.tf32.f32 %0, %1;" : "=r"(r) : "f"(f));
    return __uint_as_float(r);
}

__device__ __forceinline__ void cp_async16(uint32_t dst_smem, const void* src) {
    asm volatile("cp.async.ca.shared.global [%0], [%1], 16;"
                 :: "r"(dst_smem), "l"(src) : "memory");
}
__device__ __forceinline__ void cp_commit() {
    asm volatile("cp.async.commit_group;" ::: "memory");
}
template<int NWAIT>
__device__ __forceinline__ void cp_wait() {
    asm volatile("cp.async.wait_group %0;" :: "n"(NWAIT) : "memory");
}
__device__ __forceinline__ uint32_t smem_u32(const void* p) {
    uint32_t a;
    asm("{ .reg .u64 t; cvta.to.shared.u64 t, %1; cvt.u32.u64 %0, t; }" : "=r"(a) : "l"(p));
    return a;
}

// ---------------- kernel 1: three_nn -----------------------------------------
__global__ void knn3_kernel(const float* __restrict__ xyz1,
                            const float* __restrict__ xyz2) {
    __shared__ float4 s2[M_];
    const int b = blockIdx.y;
    const float* p2 = xyz2 + (size_t)b * M_ * 3;
    for (int j = threadIdx.x; j < M_; j += blockDim.x) {
        float x = p2[j * 3 + 0], y = p2[j * 3 + 1], z = p2[j * 3 + 2];
        s2[j] = make_float4(x, y, z, x * x + y * y + z * z);
    }
    __syncthreads();

    const int n = blockIdx.x * blockDim.x + threadIdx.x;
    const int p = b * N_ + n;
    const float* q = xyz1 + (size_t)p * 3;
    const float qx = q[0], qy = q[1], qz = q[2];
    const float qx2 = 2.0f * qx, qy2 = 2.0f * qy, qz2 = 2.0f * qz;
    const float sq1 = qx * qx + qy * qy + qz * qz;

    float k0 = 3.4e38f, k1 = 3.4e38f, k2 = 3.4e38f;
    int   i0 = 0, i1 = 0, i2 = 0;

    #pragma unroll 8
    for (int j = 0; j < M_; j++) {
        float4 v = s2[j];
        float key = v.w;
        key = fmaf(-qx2, v.x, key);
        key = fmaf(-qy2, v.y, key);
        key = fmaf(-qz2, v.z, key);
        if (key < k2) {
            if (key < k1) {
                k2 = k1; i2 = i1;
                if (key < k0) { k1 = k0; i1 = i0; k0 = key; i0 = j; }
                else          { k1 = key; i1 = j; }
            } else { k2 = key; i2 = j; }
        }
    }

    float d0 = fmaxf(k0 + sq1, 1e-10f);
    float d1 = fmaxf(k1 + sq1, 1e-10f);
    float d2 = fmaxf(k2 + sq1, 1e-10f);
    float w0 = 1.0f / d0, w1 = 1.0f / d1, w2 = 1.0f / d2;
    float inv = 1.0f / (w0 + w1 + w2);
    g_idx[p * 3 + 0] = i0; g_idx[p * 3 + 1] = i1; g_idx[p * 3 + 2] = i2;
    g_w[p * 3 + 0] = w0 * inv; g_w[p * 3 + 1] = w1 * inv; g_w[p * 3 + 2] = w2 * inv;
}

// ---------------- kernel 1b: round weights to tf32 ---------------------------
__global__ void round_weights(const float* __restrict__ W1,
                              const float* __restrict__ W2) {
    int t = blockIdx.x * blockDim.x + threadIdx.x;   // 32768 float4 slots
    const int n1 = CIN_ * H1_ / 4;                    // 24576
    if (t < n1) {
        float4 v = ((const float4*)W1)[t];
        v.x = rna_tf32(v.x); v.y = rna_tf32(v.y);
        v.z = rna_tf32(v.z); v.w = rna_tf32(v.w);
        ((float4*)g_W1r)[t] = v;
    } else {
        int u = t - n1;
        if (u < H1_ * H2_ / 4) {
            float4 v = ((const float4*)W2)[u];
            v.x = rna_tf32(v.x); v.y = rna_tf32(v.y);
            v.z = rna_tf32(v.z); v.w = rna_tf32(v.w);
            ((float4*)g_W2r)[u] = v;
        }
    }
}

// ---------------- kernel 2: interpolate + concat (tf32-rounded) --------------
__global__ void interp_kernel(const float* __restrict__ points2,
                              const float* __restrict__ points1) {
    const int warp = (blockIdx.x * blockDim.x + threadIdx.x) >> 5;
    const int lane = threadIdx.x & 31;
    if (warp >= BNPTS) return;
    const int b = warp >> 13;
    const int i0 = g_idx[warp * 3 + 0];
    const int i1 = g_idx[warp * 3 + 1];
    const int i2 = g_idx[warp * 3 + 2];
    const float w0 = g_w[warp * 3 + 0];
    const float w1 = g_w[warp * 3 + 1];
    const float w2 = g_w[warp * 3 + 2];

    const float4* base = (const float4*)(points2 + (size_t)b * M_ * C2_);
    float4* xr = (float4*)(g_x + (size_t)warp * CIN_);

    #pragma unroll
    for (int c = lane; c < C2_ / 4; c += 32) {
        float4 a = base[(size_t)i0 * (C2_ / 4) + c];
        float4 bb = base[(size_t)i1 * (C2_ / 4) + c];
        float4 cc = base[(size_t)i2 * (C2_ / 4) + c];
        float4 r;
        r.x = rna_tf32(w0 * a.x + w1 * bb.x + w2 * cc.x);
        r.y = rna_tf32(w0 * a.y + w1 * bb.y + w2 * cc.y);
        r.z = rna_tf32(w0 * a.z + w1 * bb.z + w2 * cc.z);
        r.w = rna_tf32(w0 * a.w + w1 * bb.w + w2 * cc.w);
        xr[c] = r;
    }
    const float4* p1 = (const float4*)(points1 + (size_t)warp * C1_);
    float4 v = p1[lane];
    v.x = rna_tf32(v.x); v.y = rna_tf32(v.y);
    v.z = rna_tf32(v.z); v.w = rna_tf32(v.w);
    xr[C2_ / 4 + lane] = v;
}

// ---------------- kernel 3: TF32 mma GEMM, cp.async 3-stage pipeline ---------
// C[M,Ncols] = relu(A[M,KDIM] @ W[KDIM,Ncols] + bias), operands pre-rounded.
// Tile 128x128x32, 8 warps (2M x 4N), warp tile 64x32 = 4x4 m16n8k8.
// SMEM row-major: A padded stride 36 floats, B padded stride 136 floats.
#define SA_STRIDE 36
#define SB_STRIDE 136
#define A_STG (128 * SA_STRIDE)           // 4608 floats
#define B_STG (32 * SB_STRIDE)            // 4352 floats
#define STG   (A_STG + B_STG)             // 8960 floats
#define NSTAGE 3

__device__ __forceinline__ void mma_tf32(float* c, const uint32_t* a,
                                         const uint32_t* b) {
    asm volatile(
        "mma.sync.aligned.m16n8k8.row.col.f32.tf32.tf32.f32 "
        "{%0,%1,%2,%3}, {%4,%5,%6,%7}, {%8,%9}, {%0,%1,%2,%3};"
        : "+f"(c[0]), "+f"(c[1]), "+f"(c[2]), "+f"(c[3])
        : "r"(a[0]), "r"(a[1]), "r"(a[2]), "r"(a[3]), "r"(b[0]), "r"(b[1]));
}

template<int KDIM, bool ROUND>
__global__ __launch_bounds__(256, 2)
void mma_gemm(const float* __restrict__ A, const float* __restrict__ W,
              const float* __restrict__ bias, float* __restrict__ C,
              int Ncols) {
    extern __shared__ float smem[];
    constexpr int NC = KDIM / 32;

    const int tid  = threadIdx.x;
    const int wid  = tid >> 5, lane = tid & 31;
    const int wm   = wid >> 2, wn = wid & 3;
    const int m0   = blockIdx.y * 128;
    const int n0   = blockIdx.x * 128;
    const float* Ab = A + (size_t)m0 * KDIM;

    const uint32_t sbase = smem_u32(smem);

    // per-thread cp.async source/dest precompute
    const int ar  = tid >> 1;                  // A: 128 rows, 2 threads/row
    const int af4 = (tid & 1) * 4;             // float offset 0 or 16 bytes*? (2 segs)
    // A: 1024 segs of 16B: seg = tid + i*256 -> r = seg>>3, s = seg&7
    // B: 1024 segs:                 seg -> k = seg>>5, s = seg&31

    float acc[4][4][4];
    #pragma unroll
    for (int i = 0; i < 4; i++)
        #pragma unroll
        for (int j = 0; j < 4; j++)
            #pragma unroll
            for (int e = 0; e < 4; e++) acc[i][j][e] = 0.0f;

    auto load_stage = [&](int c, int stg) {
        const uint32_t as = sbase + stg * STG * 4;
        const uint32_t bs = as + A_STG * 4;
        #pragma unroll
        for (int i = 0; i < 4; i++) {
            int seg = tid + i * 256;
            int r = seg >> 3, s = seg & 7;
            cp_async16(as + (r * SA_STRIDE + s * 4) * 4,
                       Ab + (size_t)r * KDIM + c * 32 + s * 4);
        }
        #pragma unroll
        for (int i = 0; i < 4; i++) {
            int seg = tid + i * 256;
            int k = seg >> 5, s = seg & 31;
            cp_async16(bs + (k * SB_STRIDE + s * 4) * 4,
                       W + (size_t)(c * 32 + k) * Ncols + n0 + s * 4);
        }
        cp_commit();
    };

    #pragma unroll
    for (int s = 0; s < NSTAGE - 1; s++) load_stage(s, s);

    #pragma unroll 1
    for (int c = 0; c < NC; c++) {
        cp_wait<NSTAGE - 2>();
        __syncthreads();

        const int stg = c % NSTAGE;
        const float* aS = smem + stg * STG;
        const float* bS = aS + A_STG;
        const int ql = lane >> 2, rl = lane & 3;

        #pragma unroll
        for (int ks = 0; ks < 4; ks++) {
            uint32_t af[4][4], bf[4][2];
            #pragma unroll
            for (int mt = 0; mt < 4; mt++) {
                const float* ap = aS + (wm * 64 + mt * 16 + ql) * SA_STRIDE + ks * 8 + rl;
                af[mt][0] = __float_as_uint(ap[0]);
                af[mt][1] = __float_as_uint(ap[8 * SA_STRIDE]);
                af[mt][2] = __float_as_uint(ap[4]);
                af[mt][3] = __float_as_uint(ap[8 * SA_STRIDE + 4]);
            }
            #pragma unroll
            for (int nt = 0; nt < 4; nt++) {
                const float* bp = bS + (ks * 8 + rl) * SB_STRIDE + wn * 32 + nt * 8 + ql;
                bf[nt][0] = __float_as_uint(bp[0]);
                bf[nt][1] = __float_as_uint(bp[4 * SB_STRIDE]);
            }
            #pragma unroll
            for (int mt = 0; mt < 4; mt++)
                #pragma unroll
                for (int nt = 0; nt < 4; nt++)
                    mma_tf32(acc[mt][nt], af[mt], bf[nt]);
        }

        __syncthreads();
        if (c + NSTAGE - 1 < NC) load_stage(c + NSTAGE - 1, (c + NSTAGE - 1) % NSTAGE);
        else cp_commit();   // keep group count uniform for wait_group
    }

    // ---- epilogue: bias + relu (+ tf32 round for layer-1 output) ----
    #pragma unroll
    for (int nt = 0; nt < 4; nt++) {
        const int colb = n0 + wn * 32 + nt * 8 + (lane & 3) * 2;
        float2 bv = *(const float2*)(bias + colb);
        #pragma unroll
        for (int mt = 0; mt < 4; mt++) {
            const int row0 = m0 + wm * 64 + mt * 16 + (lane >> 2);
            float v0 = fmaxf(acc[mt][nt][0] + bv.x, 0.0f);
            float v1 = fmaxf(acc[mt][nt][1] + bv.y, 0.0f);
            float v2 = fmaxf(acc[mt][nt][2] + bv.x, 0.0f);
            float v3 = fmaxf(acc[mt][nt][3] + bv.y, 0.0f);
            if (ROUND) {
                v0 = rna_tf32(v0); v1 = rna_tf32(v1);
                v2 = rna_tf32(v2); v3 = rna_tf32(v3);
            }
            *(float2*)(C + (size_t)row0 * Ncols + colb)       = make_float2(v0, v1);
            *(float2*)(C + (size_t)(row0 + 8) * Ncols + colb) = make_float2(v2, v3);
        }
    }
}

// ---------------- launch ------------------------------------------------------
extern "C" void kernel_launch(void* const* d_in, const int* in_sizes, int n_in,
                              void* d_out, int out_size) {
    const float* xyz1    = (const float*)d_in[0];
    const float* xyz2    = (const float*)d_in[1];
    const float* points1 = (const float*)d_in[2];
    const float* points2 = (const float*)d_in[3];
    const float* W1      = (const float*)d_in[4];
    const float* b1      = (const float*)d_in[5];
    const float* W2      = (const float*)d_in[6];
    const float* b2      = (const float*)d_in[7];
    float* out = (float*)d_out;

    float *gx, *gh, *gw1, *gw2;
    cudaGetSymbolAddress((void**)&gx,  g_x);
    cudaGetSymbolAddress((void**)&gh,  g_h);
    cudaGetSymbolAddress((void**)&gw1, g_W1r);
    cudaGetSymbolAddress((void**)&gw2, g_W2r);

    const int smem = NSTAGE * STG * 4;   // 107520 bytes
    cudaFuncSetAttribute(mma_gemm<CIN_, true>,
                         cudaFuncAttributeMaxDynamicSharedMemorySize, smem);
    cudaFuncSetAttribute(mma_gemm<H1_, false>,
                         cudaFuncAttributeMaxDynamicSharedMemorySize, smem);

    // 1) three_nn  +  weight rounding (independent)
    dim3 g1(N_ / 256, B_);
    knn3_kernel<<<g1, 256>>>(xyz1, xyz2);
    round_weights<<<((CIN_ * H1_ + H1_ * H2_) / 4 + 255) / 256, 256>>>(W1, W2);

    // 2) interpolate + concat
    interp_kernel<<<BNPTS / 8, 256>>>(points2, points1);

    // 3) layer 1: relu(g_x[65536,384] @ W1[384,256] + b1) -> g_h (tf32-rounded)
    dim3 g3(H1_ / 128, BNPTS / 128);
    mma_gemm<CIN_, true><<<g3, 256, smem>>>(gx, gw1, b1, gh, H1_);

    // 4) layer 2: relu(g_h[65536,256] @ W2[256,128] + b2) -> out
    dim3 g4(H2_ / 128, BNPTS / 128);
    mma_gemm<H1_, false><<<g4, 256, smem>>>(gh, gw2, b2, out, H2_);
}

// round 6
// speedup vs baseline: 2.6284x; 1.1630x over previous
#include <cuda_runtime.h>
#include <cstdint>

#define B_    8
#define N_    8192
#define M_    2048
#define C1_   128
#define C2_   256
#define H1_   256
#define H2_   128
#define CIN_  (C2_ + C1_)   // 384
#define BNPTS (B_ * N_)     // 65536
#define NC1   12            // K chunks layer 1 (384/32)
#define NC2   8             // K chunks layer 2 (256/32)

// strides (floats) chosen so LDS fragment banks are conflict-free
#define SA   36     // A tile row stride   (36 % 32 == 4)
#define SB1  264    // B1 chunk row stride (264 % 32 == 8)
#define SB2  136    // W2 chunk row stride (136 % 32 == 8)
#define HSTR 260    // h row stride        (260 % 32 == 4)

// union-region float offsets (relative to U)
#define A_BUFSZ  (128 * SA)     // 4608 floats
#define B1_BUFSZ (32 * SB1)     // 8448
#define W2_BUFSZ (32 * SB2)     // 4352
#define OFF_A0   0
#define OFF_A1   (A_BUFSZ)
#define OFF_B1   (2 * A_BUFSZ)            // 9216, three bufs
#define OFF_H    0                        // h overlays phase-1 stages
#define OFF_W2   (128 * HSTR)             // 33280, three bufs
#define U_FLOATS (OFF_W2 + 3 * W2_BUFSZ)  // 46336 floats = 185344 B
#define META_FLOATS 1152                  // idx 384(int) + w 384 + b1 256 + b2 128
#define SMEM_BYTES ((META_FLOATS + U_FLOATS) * 4)   // 189952

// ---------------- scratch ----------------------------------------------------
__device__ int   g_idx[BNPTS * 3];
__device__ float g_w[BNPTS * 3];
__device__ float g_W1r[CIN_ * H1_];   // tf32-rounded W1 row-major
__device__ float g_W2r[H1_ * H2_];    // tf32-rounded W2 row-major

__device__ __forceinline__ float rna_tf32(float f) {
    uint32_t r;
    asm("cvt.rna.tf32.f32 %0, %1;" : "=r"(r) : "f"(f));
    return __uint_as_float(r);
}
__device__ __forceinline__ void cp_async16(uint32_t dst, const void* src) {
    asm volatile("cp.async.ca.shared.global [%0], [%1], 16;"
                 :: "r"(dst), "l"(src) : "memory");
}
__device__ __forceinline__ void cp_commit() {
    asm volatile("cp.async.commit_group;" ::: "memory");
}
template<int NWAIT>
__device__ __forceinline__ void cp_wait() {
    asm volatile("cp.async.wait_group %0;" :: "n"(NWAIT) : "memory");
}
__device__ __forceinline__ uint32_t smem_u32(const void* p) {
    uint32_t a;
    asm("{ .reg .u64 t; cvta.to.shared.u64 t, %1; cvt.u32.u64 %0, t; }" : "=r"(a) : "l"(p));
    return a;
}
__device__ __forceinline__ void mma_tf32(float* c, const uint32_t* a,
                                         const uint32_t* b) {
    asm volatile(
        "mma.sync.aligned.m16n8k8.row.col.f32.tf32.tf32.f32 "
        "{%0,%1,%2,%3}, {%4,%5,%6,%7}, {%8,%9}, {%0,%1,%2,%3};"
        : "+f"(c[0]), "+f"(c[1]), "+f"(c[2]), "+f"(c[3])
        : "r"(a[0]), "r"(a[1]), "r"(a[2]), "r"(a[3]), "r"(b[0]), "r"(b[1]));
}

// ---------------- kernel 1: three_nn -----------------------------------------
__global__ void knn3_kernel(const float* __restrict__ xyz1,
                            const float* __restrict__ xyz2) {
    __shared__ float4 s2[M_];
    const int b = blockIdx.y;
    const float* p2 = xyz2 + (size_t)b * M_ * 3;
    for (int j = threadIdx.x; j < M_; j += blockDim.x) {
        float x = p2[j * 3 + 0], y = p2[j * 3 + 1], z = p2[j * 3 + 2];
        s2[j] = make_float4(x, y, z, x * x + y * y + z * z);
    }
    __syncthreads();

    const int n = blockIdx.x * blockDim.x + threadIdx.x;
    const int p = b * N_ + n;
    const float* q = xyz1 + (size_t)p * 3;
    const float qx = q[0], qy = q[1], qz = q[2];
    const float qx2 = 2.0f * qx, qy2 = 2.0f * qy, qz2 = 2.0f * qz;
    const float sq1 = qx * qx + qy * qy + qz * qz;

    float k0 = 3.4e38f, k1 = 3.4e38f, k2 = 3.4e38f;
    int   i0 = 0, i1 = 0, i2 = 0;

    #pragma unroll 8
    for (int j = 0; j < M_; j++) {
        float4 v = s2[j];
        float key = v.w;
        key = fmaf(-qx2, v.x, key);
        key = fmaf(-qy2, v.y, key);
        key = fmaf(-qz2, v.z, key);
        if (key < k2) {
            if (key < k1) {
                k2 = k1; i2 = i1;
                if (key < k0) { k1 = k0; i1 = i0; k0 = key; i0 = j; }
                else          { k1 = key; i1 = j; }
            } else { k2 = key; i2 = j; }
        }
    }

    float d0 = fmaxf(k0 + sq1, 1e-10f);
    float d1 = fmaxf(k1 + sq1, 1e-10f);
    float d2 = fmaxf(k2 + sq1, 1e-10f);
    float w0 = 1.0f / d0, w1 = 1.0f / d1, w2 = 1.0f / d2;
    float inv = 1.0f / (w0 + w1 + w2);
    g_idx[p * 3 + 0] = i0; g_idx[p * 3 + 1] = i1; g_idx[p * 3 + 2] = i2;
    g_w[p * 3 + 0] = w0 * inv; g_w[p * 3 + 1] = w1 * inv; g_w[p * 3 + 2] = w2 * inv;
}

// ---------------- kernel 1b: round weights to tf32 ---------------------------
__global__ void round_weights(const float* __restrict__ W1,
                              const float* __restrict__ W2) {
    int t = blockIdx.x * blockDim.x + threadIdx.x;
    const int n1 = CIN_ * H1_ / 4;
    if (t < n1) {
        float4 v = ((const float4*)W1)[t];
        v.x = rna_tf32(v.x); v.y = rna_tf32(v.y);
        v.z = rna_tf32(v.z); v.w = rna_tf32(v.w);
        ((float4*)g_W1r)[t] = v;
    } else {
        int u = t - n1;
        if (u < H1_ * H2_ / 4) {
            float4 v = ((const float4*)W2)[u];
            v.x = rna_tf32(v.x); v.y = rna_tf32(v.y);
            v.z = rna_tf32(v.z); v.w = rna_tf32(v.w);
            ((float4*)g_W2r)[u] = v;
        }
    }
}

// ---------------- kernel 2: fused interp + MLP1 + MLP2 -----------------------
// One CTA = 128 points. Phase 1: h = relu(concat(interp,p1) @ W1 + b1) (tf32,
// kept in SMEM). Phase 2: out = relu(h @ W2 + b2).
__global__ __launch_bounds__(256, 1)
void fused_mlp(const float* __restrict__ points1,
               const float* __restrict__ points2,
               const float* __restrict__ b1,
               const float* __restrict__ b2,
               float* __restrict__ out) {
    extern __shared__ float smem[];
    int*   sIdx = (int*)smem;          // [384]
    float* sW   = smem + 384;          // [384]
    float* sB1  = smem + 768;          // [256]
    float* sB2  = smem + 1024;         // [128]
    float* U    = smem + META_FLOATS;

    const int tid = threadIdx.x;
    const int wid = tid >> 5, lane = tid & 31;
    const int wm = wid >> 2, wn = wid & 3;
    const int ql = lane >> 2, rl = lane & 3;
    const int R0 = blockIdx.x * 128;
    const int batch = R0 >> 13;        // whole tile in one batch (128 | 8192)

    // ---- meta ----
    for (int i = tid; i < 384; i += 256) {
        sIdx[i] = g_idx[R0 * 3 + i];
        sW[i]   = g_w[R0 * 3 + i];
    }
    sB1[tid & 255] = b1[tid & 255];
    if (tid < 128) sB2[tid] = b2[tid];
    __syncthreads();

    // ---- per-thread producer setup (2 threads per point) ----
    const int pr  = tid >> 1;           // point 0..127
    const int pf0 = (tid & 1) * 4;      // float4 slot base (0 or 4)
    const float* pb = points2 + (size_t)batch * M_ * C2_;
    const float* n0p = pb + (size_t)sIdx[pr * 3 + 0] * C2_;
    const float* n1p = pb + (size_t)sIdx[pr * 3 + 1] * C2_;
    const float* n2p = pb + (size_t)sIdx[pr * 3 + 2] * C2_;
    const float  pw0 = sW[pr * 3 + 0], pw1 = sW[pr * 3 + 1], pw2 = sW[pr * 3 + 2];
    const float* p1row = points1 + (size_t)(R0 + pr) * C1_;

    float4 ra0[4], ra1[4], ra2[4];

    auto ldg_chunk = [&](int c) {
        if (c < 8) {
            const int off = c * 32 + pf0 * 4;
            #pragma unroll
            for (int j = 0; j < 4; j++) {
                ra0[j] = *(const float4*)(n0p + off + j * 4);
                ra1[j] = *(const float4*)(n1p + off + j * 4);
                ra2[j] = *(const float4*)(n2p + off + j * 4);
            }
        } else {
            const int off = (c - 8) * 32 + pf0 * 4;
            #pragma unroll
            for (int j = 0; j < 4; j++)
                ra0[j] = *(const float4*)(p1row + off + j * 4);
        }
    };
    auto sts_chunk = [&](int c, float* Ab) {
        float* d = Ab + pr * SA + pf0 * 4;
        if (c < 8) {
            #pragma unroll
            for (int j = 0; j < 4; j++) {
                float4 v;
                v.x = rna_tf32(fmaf(pw0, ra0[j].x, fmaf(pw1, ra1[j].x, pw2 * ra2[j].x)));
                v.y = rna_tf32(fmaf(pw0, ra0[j].y, fmaf(pw1, ra1[j].y, pw2 * ra2[j].y)));
                v.z = rna_tf32(fmaf(pw0, ra0[j].z, fmaf(pw1, ra1[j].z, pw2 * ra2[j].z)));
                v.w = rna_tf32(fmaf(pw0, ra0[j].w, fmaf(pw1, ra1[j].w, pw2 * ra2[j].w)));
                *(float4*)(d + j * 4) = v;
            }
        } else {
            #pragma unroll
            for (int j = 0; j < 4; j++) {
                float4 v = ra0[j];
                v.x = rna_tf32(v.x); v.y = rna_tf32(v.y);
                v.z = rna_tf32(v.z); v.w = rna_tf32(v.w);
                *(float4*)(d + j * 4) = v;
            }
        }
    };
    auto ldB1 = [&](int c) {
        if (c < NC1) {
            float* dst = U + OFF_B1 + (c % 3) * B1_BUFSZ;
            const float* src = g_W1r + (size_t)c * 32 * H1_;
            const uint32_t da = smem_u32(dst);
            #pragma unroll
            for (int i = 0; i < 8; i++) {
                int seg = tid + i * 256;
                int k = seg >> 6, s = (seg & 63) * 4;
                cp_async16(da + (k * SB1 + s) * 4, src + k * H1_ + s);
            }
        }
        cp_commit();
    };
    auto ldW2 = [&](int c) {
        if (c < NC2) {
            float* dst = U + OFF_W2 + (c % 3) * W2_BUFSZ;
            const float* src = g_W2r + (size_t)c * 32 * H2_;
            const uint32_t da = smem_u32(dst);
            #pragma unroll
            for (int i = 0; i < 4; i++) {
                int seg = tid + i * 256;
                int k = seg >> 5, s = (seg & 31) * 4;
                cp_async16(da + (k * SB2 + s) * 4, src + k * H2_ + s);
            }
        }
        cp_commit();
    };

    // ---- phase 1 accumulators: warp tile 64x64, frags 4(m) x 8(n) ----
    float acc[4][8][4];
    #pragma unroll
    for (int i = 0; i < 4; i++)
        #pragma unroll
        for (int j = 0; j < 8; j++)
            #pragma unroll
            for (int e = 0; e < 4; e++) acc[i][j][e] = 0.0f;

    // prologue
    ldg_chunk(0);
    sts_chunk(0, U + OFF_A0);
    ldB1(0);
    ldB1(1);

    #pragma unroll 1
    for (int c = 0; c < NC1; c++) {
        cp_wait<1>();
        __syncthreads();
        if (c + 1 < NC1) ldg_chunk(c + 1);

        const float* aS = U + ((c & 1) ? OFF_A1 : OFF_A0);
        const float* bS = U + OFF_B1 + (c % 3) * B1_BUFSZ;
        #pragma unroll
        for (int ks = 0; ks < 4; ks++) {
            uint32_t af[4][4], bf[8][2];
            #pragma unroll
            for (int mt = 0; mt < 4; mt++) {
                const float* ap = aS + (wm * 64 + mt * 16 + ql) * SA + ks * 8 + rl;
                af[mt][0] = __float_as_uint(ap[0]);
                af[mt][1] = __float_as_uint(ap[8 * SA]);
                af[mt][2] = __float_as_uint(ap[4]);
                af[mt][3] = __float_as_uint(ap[8 * SA + 4]);
            }
            #pragma unroll
            for (int nt = 0; nt < 8; nt++) {
                const float* bp = bS + (ks * 8 + rl) * SB1 + wn * 64 + nt * 8 + ql;
                bf[nt][0] = __float_as_uint(bp[0]);
                bf[nt][1] = __float_as_uint(bp[4 * SB1]);
            }
            #pragma unroll
            for (int mt = 0; mt < 4; mt++)
                #pragma unroll
                for (int nt = 0; nt < 8; nt++)
                    mma_tf32(acc[mt][nt], af[mt], bf[nt]);
        }

        if (c + 1 < NC1) sts_chunk(c + 1, U + (((c + 1) & 1) ? OFF_A1 : OFF_A0));
        ldB1(c + 2);
    }

    cp_wait<0>();
    __syncthreads();

    // ---- phase-1 epilogue: bias+relu+round -> h in SMEM; prefetch W2 ----
    float* hS = U + OFF_H;
    #pragma unroll
    for (int nt = 0; nt < 8; nt++) {
        const int cb = wn * 64 + nt * 8 + rl * 2;
        const float bx = sB1[cb], by = sB1[cb + 1];
        #pragma unroll
        for (int mt = 0; mt < 4; mt++) {
            const int r0 = wm * 64 + mt * 16 + ql;
            float v0 = rna_tf32(fmaxf(acc[mt][nt][0] + bx, 0.0f));
            float v1 = rna_tf32(fmaxf(acc[mt][nt][1] + by, 0.0f));
            float v2 = rna_tf32(fmaxf(acc[mt][nt][2] + bx, 0.0f));
            float v3 = rna_tf32(fmaxf(acc[mt][nt][3] + by, 0.0f));
            hS[r0 * HSTR + cb]           = v0;
            hS[r0 * HSTR + cb + 1]       = v1;
            hS[(r0 + 8) * HSTR + cb]     = v2;
            hS[(r0 + 8) * HSTR + cb + 1] = v3;
        }
    }
    ldW2(0);
    ldW2(1);
    __syncthreads();

    // ---- phase 2: out = relu(h @ W2 + b2); warp tile 64x32, frags 4x4 ----
    float acc2[4][4][4];
    #pragma unroll
    for (int i = 0; i < 4; i++)
        #pragma unroll
        for (int j = 0; j < 4; j++)
            #pragma unroll
            for (int e = 0; e < 4; e++) acc2[i][j][e] = 0.0f;

    #pragma unroll 1
    for (int nc = 0; nc < NC2; nc++) {
        cp_wait<1>();
        __syncthreads();
        const float* bS = U + OFF_W2 + (nc % 3) * W2_BUFSZ;
        #pragma unroll
        for (int ks = 0; ks < 4; ks++) {
            uint32_t af[4][4], bf[4][2];
            #pragma unroll
            for (int mt = 0; mt < 4; mt++) {
                const float* ap = hS + (wm * 64 + mt * 16 + ql) * HSTR
                                + nc * 32 + ks * 8 + rl;
                af[mt][0] = __float_as_uint(ap[0]);
                af[mt][1] = __float_as_uint(ap[8 * HSTR]);
                af[mt][2] = __float_as_uint(ap[4]);
                af[mt][3] = __float_as_uint(ap[8 * HSTR + 4]);
            }
            #pragma unroll
            for (int nt = 0; nt < 4; nt++) {
                const float* bp = bS + (ks * 8 + rl) * SB2 + wn * 32 + nt * 8 + ql;
                bf[nt][0] = __float_as_uint(bp[0]);
                bf[nt][1] = __float_as_uint(bp[4 * SB2]);
            }
            #pragma unroll
            for (int mt = 0; mt < 4; mt++)
                #pragma unroll
                for (int nt = 0; nt < 4; nt++)
                    mma_tf32(acc2[mt][nt], af[mt], bf[nt]);
        }
        ldW2(nc + 2);
    }

    // ---- phase-2 epilogue: bias + relu -> gmem ----
    float* outB = out + (size_t)R0 * H2_;
    #pragma unroll
    for (int nt = 0; nt < 4; nt++) {
        const int cb = wn * 32 + nt * 8 + rl * 2;
        const float bx = sB2[cb], by = sB2[cb + 1];
        #pragma unroll
        for (int mt = 0; mt < 4; mt++) {
            const int r0 = wm * 64 + mt * 16 + ql;
            float v0 = fmaxf(acc2[mt][nt][0] + bx, 0.0f);
            float v1 = fmaxf(acc2[mt][nt][1] + by, 0.0f);
            float v2 = fmaxf(acc2[mt][nt][2] + bx, 0.0f);
            float v3 = fmaxf(acc2[mt][nt][3] + by, 0.0f);
            *(float2*)(outB + (size_t)r0 * H2_ + cb)       = make_float2(v0, v1);
            *(float2*)(outB + (size_t)(r0 + 8) * H2_ + cb) = make_float2(v2, v3);
        }
    }
}

// ---------------- launch ------------------------------------------------------
extern "C" void kernel_launch(void* const* d_in, const int* in_sizes, int n_in,
                              void* d_out, int out_size) {
    const float* xyz1    = (const float*)d_in[0];
    const float* xyz2    = (const float*)d_in[1];
    const float* points1 = (const float*)d_in[2];
    const float* points2 = (const float*)d_in[3];
    const float* W1      = (const float*)d_in[4];
    const float* b1      = (const float*)d_in[5];
    const float* W2      = (const float*)d_in[6];
    const float* b2      = (const float*)d_in[7];
    float* out = (float*)d_out;

    cudaFuncSetAttribute(fused_mlp,
                         cudaFuncAttributeMaxDynamicSharedMemorySize, SMEM_BYTES);

    // 1) weight prep + three_nn
    round_weights<<<((CIN_ * H1_ + H1_ * H2_) / 4 + 255) / 256, 256>>>(W1, W2);
    dim3 g1(N_ / 256, B_);
    knn3_kernel<<<g1, 256>>>(xyz1, xyz2);

    // 2) fused interp + MLP (512 CTAs of 128 points)
    fused_mlp<<<BNPTS / 128, 256, SMEM_BYTES>>>(points1, points2, b1, b2, out);
}

// round 7
// speedup vs baseline: 3.2425x; 1.2337x over previous
#include <cuda_runtime.h>
#include <cuda_fp16.h>
#include <cstdint>

#define B_    8
#define N_    8192
#define M_    2048
#define C1_   128
#define C2_   256
#define H1_   256
#define H2_   128
#define CIN_  (C2_ + C1_)   // 384
#define BNPTS (B_ * N_)     // 65536
#define NC1   12            // K chunks layer 1 (384/32)
#define NC2   8             // K chunks layer 2 (256/32)

// strides in HALVES, chosen conflict-free for half2 fragment loads
#define SA_H   40    // A / B1 / W2 chunk row stride (40 halves = 20 words)
#define HSTR_H 264   // h row stride (264 halves = 132 words, %32 == 4 words)

#define A_BUFH  (128 * SA_H)     // 5120 halves
#define B1_BUFH (256 * SA_H)     // 10240
#define W2_BUFH (128 * SA_H)     // 5120
#define OFF_A0  0
#define OFF_A1  A_BUFH
#define OFF_B1  (2 * A_BUFH)               // 10240, 3 bufs
#define OFF_H   0                          // overlays phase-1 buffers
#define OFF_W2  (128 * HSTR_H)             // 33792, 3 bufs
#define U_HALVES (OFF_W2 + 3 * W2_BUFH)    // 49152 halves = 98304 B
#define META_FLOATS 1152
#define SMEM_BYTES (META_FLOATS * 4 + U_HALVES * 2)   // 102912

// ---------------- scratch ----------------------------------------------------
__device__ int    g_idx[BNPTS * 3];
__device__ float  g_w[BNPTS * 3];
__device__ __half g_W1t[H1_ * CIN_];   // W1^T [256 n][384 k], half, k contiguous
__device__ __half g_W2t[H2_ * H1_];    // W2^T [128 n][256 k]

__device__ __forceinline__ void cp_async16(uint32_t dst, const void* src) {
    asm volatile("cp.async.ca.shared.global [%0], [%1], 16;"
                 :: "r"(dst), "l"(src) : "memory");
}
__device__ __forceinline__ void cp_commit() {
    asm volatile("cp.async.commit_group;" ::: "memory");
}
template<int NWAIT>
__device__ __forceinline__ void cp_wait() {
    asm volatile("cp.async.wait_group %0;" :: "n"(NWAIT) : "memory");
}
__device__ __forceinline__ uint32_t smem_u32(const void* p) {
    uint32_t a;
    asm("{ .reg .u64 t; cvta.to.shared.u64 t, %1; cvt.u32.u64 %0, t; }" : "=r"(a) : "l"(p));
    return a;
}
__device__ __forceinline__ void mma_f16(float* c, const uint32_t* a,
                                        const uint32_t* b) {
    asm volatile(
        "mma.sync.aligned.m16n8k16.row.col.f32.f16.f16.f32 "
        "{%0,%1,%2,%3}, {%4,%5,%6,%7}, {%8,%9}, {%0,%1,%2,%3};"
        : "+f"(c[0]), "+f"(c[1]), "+f"(c[2]), "+f"(c[3])
        : "r"(a[0]), "r"(a[1]), "r"(a[2]), "r"(a[3]), "r"(b[0]), "r"(b[1]));
}

// ---------------- kernel 1: three_nn -----------------------------------------
__global__ void knn3_kernel(const float* __restrict__ xyz1,
                            const float* __restrict__ xyz2) {
    __shared__ float4 s2[M_];
    const int b = blockIdx.y;
    const float* p2 = xyz2 + (size_t)b * M_ * 3;
    for (int j = threadIdx.x; j < M_; j += blockDim.x) {
        float x = p2[j * 3 + 0], y = p2[j * 3 + 1], z = p2[j * 3 + 2];
        s2[j] = make_float4(x, y, z, x * x + y * y + z * z);
    }
    __syncthreads();

    const int n = blockIdx.x * blockDim.x + threadIdx.x;
    const int p = b * N_ + n;
    const float* q = xyz1 + (size_t)p * 3;
    const float qx = q[0], qy = q[1], qz = q[2];
    const float qx2 = 2.0f * qx, qy2 = 2.0f * qy, qz2 = 2.0f * qz;
    const float sq1 = qx * qx + qy * qy + qz * qz;

    float k0 = 3.4e38f, k1 = 3.4e38f, k2 = 3.4e38f;
    int   i0 = 0, i1 = 0, i2 = 0;

    #pragma unroll 8
    for (int j = 0; j < M_; j++) {
        float4 v = s2[j];
        float key = v.w;
        key = fmaf(-qx2, v.x, key);
        key = fmaf(-qy2, v.y, key);
        key = fmaf(-qz2, v.z, key);
        if (key < k2) {
            if (key < k1) {
                k2 = k1; i2 = i1;
                if (key < k0) { k1 = k0; i1 = i0; k0 = key; i0 = j; }
                else          { k1 = key; i1 = j; }
            } else { k2 = key; i2 = j; }
        }
    }

    float d0 = fmaxf(k0 + sq1, 1e-10f);
    float d1 = fmaxf(k1 + sq1, 1e-10f);
    float d2 = fmaxf(k2 + sq1, 1e-10f);
    float w0 = 1.0f / d0, w1 = 1.0f / d1, w2 = 1.0f / d2;
    float inv = 1.0f / (w0 + w1 + w2);
    g_idx[p * 3 + 0] = i0; g_idx[p * 3 + 1] = i1; g_idx[p * 3 + 2] = i2;
    g_w[p * 3 + 0] = w0 * inv; g_w[p * 3 + 1] = w1 * inv; g_w[p * 3 + 2] = w2 * inv;
}

// ---------------- kernel 1b: transpose W -> half, [N][K] ---------------------
// block (32,8), tile 32x32. In: W[K][N] f32. Out: Wt[N][K] half.
__global__ void transpose_half(const float* __restrict__ W, __half* __restrict__ Wt,
                               int K, int Ncols) {
    __shared__ float t[32][33];
    const int k0 = blockIdx.x * 32, n0 = blockIdx.y * 32;
    const int tx = threadIdx.x, ty = threadIdx.y;
    #pragma unroll
    for (int j = 0; j < 4; j++)
        t[ty + j * 8][tx] = W[(size_t)(k0 + ty + j * 8) * Ncols + n0 + tx];
    __syncthreads();
    #pragma unroll
    for (int j = 0; j < 4; j++)
        Wt[(size_t)(n0 + ty + j * 8) * K + k0 + tx] = __float2half_rn(t[tx][ty + j * 8]);
}

// ---------------- kernel 2: fused interp + MLP1 + MLP2 (fp16 MMA) ------------
__global__ __launch_bounds__(256, 1)
void fused_mlp(const float* __restrict__ points1,
               const float* __restrict__ points2,
               const float* __restrict__ b1,
               const float* __restrict__ b2,
               float* __restrict__ out) {
    extern __shared__ float smem[];
    int*    sIdx = (int*)smem;          // [384]
    float*  sW   = smem + 384;          // [384]
    float*  sB1  = smem + 768;          // [256]
    float*  sB2  = smem + 1024;         // [128]
    __half* U    = (__half*)(smem + META_FLOATS);

    const int tid = threadIdx.x;
    const int wid = tid >> 5, lane = tid & 31;
    const int wm = wid >> 2, wn = wid & 3;
    const int ql = lane >> 2, rl = lane & 3;
    const int R0 = blockIdx.x * 128;
    const int batch = R0 >> 13;

    for (int i = tid; i < 384; i += 256) {
        sIdx[i] = g_idx[R0 * 3 + i];
        sW[i]   = g_w[R0 * 3 + i];
    }
    sB1[tid] = b1[tid];
    if (tid < 128) sB2[tid] = b2[tid];
    __syncthreads();

    // ---- producer setup: 2 threads / point, 16 halves each per 32-chunk ----
    const int pr  = tid >> 1;
    const int hf0 = (tid & 1) * 16;     // half offset within chunk
    const float* pb = points2 + (size_t)batch * M_ * C2_;
    const float* n0p = pb + (size_t)sIdx[pr * 3 + 0] * C2_;
    const float* n1p = pb + (size_t)sIdx[pr * 3 + 1] * C2_;
    const float* n2p = pb + (size_t)sIdx[pr * 3 + 2] * C2_;
    const float  pw0 = sW[pr * 3 + 0], pw1 = sW[pr * 3 + 1], pw2 = sW[pr * 3 + 2];
    const float* p1row = points1 + (size_t)(R0 + pr) * C1_;

    float4 ra0[4], ra1[4], ra2[4];

    auto ldg_chunk = [&](int c) {
        if (c < 8) {
            const int off = c * 32 + hf0;
            #pragma unroll
            for (int j = 0; j < 4; j++) {
                ra0[j] = *(const float4*)(n0p + off + j * 4);
                ra1[j] = *(const float4*)(n1p + off + j * 4);
                ra2[j] = *(const float4*)(n2p + off + j * 4);
            }
        } else {
            const int off = (c - 8) * 32 + hf0;
            #pragma unroll
            for (int j = 0; j < 4; j++)
                ra0[j] = *(const float4*)(p1row + off + j * 4);
        }
    };
    auto sts_chunk = [&](int c, __half* Ab) {
        __half2 h2[8];
        if (c < 8) {
            #pragma unroll
            for (int j = 0; j < 4; j++) {
                float x = fmaf(pw0, ra0[j].x, fmaf(pw1, ra1[j].x, pw2 * ra2[j].x));
                float y = fmaf(pw0, ra0[j].y, fmaf(pw1, ra1[j].y, pw2 * ra2[j].y));
                float z = fmaf(pw0, ra0[j].z, fmaf(pw1, ra1[j].z, pw2 * ra2[j].z));
                float w = fmaf(pw0, ra0[j].w, fmaf(pw1, ra1[j].w, pw2 * ra2[j].w));
                h2[j * 2 + 0] = __floats2half2_rn(x, y);
                h2[j * 2 + 1] = __floats2half2_rn(z, w);
            }
        } else {
            #pragma unroll
            for (int j = 0; j < 4; j++) {
                h2[j * 2 + 0] = __floats2half2_rn(ra0[j].x, ra0[j].y);
                h2[j * 2 + 1] = __floats2half2_rn(ra0[j].z, ra0[j].w);
            }
        }
        uint4* d = (uint4*)(Ab + pr * SA_H + hf0);
        d[0] = *(uint4*)&h2[0];
        d[1] = *(uint4*)&h2[4];
    };
    auto ldB1 = [&](int c) {
        if (c < NC1) {
            __half* dst = U + OFF_B1 + (c % 3) * B1_BUFH;
            const __half* src = g_W1t + c * 32;
            const uint32_t da = smem_u32(dst);
            #pragma unroll
            for (int i = 0; i < 4; i++) {
                int seg = tid + i * 256;
                int n = seg >> 2, s = seg & 3;
                cp_async16(da + (n * SA_H + s * 8) * 2,
                           src + (size_t)n * CIN_ + s * 8);
            }
        }
        cp_commit();
    };
    auto ldW2 = [&](int c) {
        if (c < NC2) {
            __half* dst = U + OFF_W2 + (c % 3) * W2_BUFH;
            const __half* src = g_W2t + c * 32;
            const uint32_t da = smem_u32(dst);
            #pragma unroll
            for (int i = 0; i < 2; i++) {
                int seg = tid + i * 256;
                int n = seg >> 2, s = seg & 3;
                cp_async16(da + (n * SA_H + s * 8) * 2,
                           src + (size_t)n * H1_ + s * 8);
            }
        }
        cp_commit();
    };

    // ---- phase 1: warp tile 64x64, frags 4(m) x 8(n), K=16/mma ----
    float acc[4][8][4];
    #pragma unroll
    for (int i = 0; i < 4; i++)
        #pragma unroll
        for (int j = 0; j < 8; j++)
            #pragma unroll
            for (int e = 0; e < 4; e++) acc[i][j][e] = 0.0f;

    ldg_chunk(0);
    sts_chunk(0, U + OFF_A0);
    ldB1(0);
    ldB1(1);

    #pragma unroll 1
    for (int c = 0; c < NC1; c++) {
        cp_wait<1>();
        __syncthreads();
        if (c + 1 < NC1) ldg_chunk(c + 1);

        const __half* aS = U + ((c & 1) ? OFF_A1 : OFF_A0);
        const __half* bS = U + OFF_B1 + (c % 3) * B1_BUFH;
        #pragma unroll
        for (int ks = 0; ks < 2; ks++) {
            uint32_t af[4][4], bf[8][2];
            #pragma unroll
            for (int mt = 0; mt < 4; mt++) {
                const __half* ap = aS + (wm * 64 + mt * 16 + ql) * SA_H + ks * 16 + rl * 2;
                af[mt][0] = *(const uint32_t*)(ap);
                af[mt][1] = *(const uint32_t*)(ap + 8 * SA_H);
                af[mt][2] = *(const uint32_t*)(ap + 8);
                af[mt][3] = *(const uint32_t*)(ap + 8 * SA_H + 8);
            }
            #pragma unroll
            for (int nt = 0; nt < 8; nt++) {
                const __half* bp = bS + (wn * 64 + nt * 8 + ql) * SA_H + ks * 16 + rl * 2;
                bf[nt][0] = *(const uint32_t*)(bp);
                bf[nt][1] = *(const uint32_t*)(bp + 8);
            }
            #pragma unroll
            for (int mt = 0; mt < 4; mt++)
                #pragma unroll
                for (int nt = 0; nt < 8; nt++)
                    mma_f16(acc[mt][nt], af[mt], bf[nt]);
        }

        if (c + 1 < NC1) sts_chunk(c + 1, U + (((c + 1) & 1) ? OFF_A1 : OFF_A0));
        ldB1(c + 2);
    }

    cp_wait<0>();
    __syncthreads();

    // ---- phase-1 epilogue: bias+relu -> h (half, SMEM); prefetch W2 ----
    __half* hS = U + OFF_H;
    #pragma unroll
    for (int nt = 0; nt < 8; nt++) {
        const int cb = wn * 64 + nt * 8 + rl * 2;
        const float bx = sB1[cb], by = sB1[cb + 1];
        #pragma unroll
        for (int mt = 0; mt < 4; mt++) {
            const int r0 = wm * 64 + mt * 16 + ql;
            *(__half2*)(hS + r0 * HSTR_H + cb) =
                __floats2half2_rn(fmaxf(acc[mt][nt][0] + bx, 0.0f),
                                  fmaxf(acc[mt][nt][1] + by, 0.0f));
            *(__half2*)(hS + (r0 + 8) * HSTR_H + cb) =
                __floats2half2_rn(fmaxf(acc[mt][nt][2] + bx, 0.0f),
                                  fmaxf(acc[mt][nt][3] + by, 0.0f));
        }
    }
    ldW2(0);
    ldW2(1);
    __syncthreads();

    // ---- phase 2: out = relu(h @ W2 + b2); warp tile 64x32 ----
    float acc2[4][4][4];
    #pragma unroll
    for (int i = 0; i < 4; i++)
        #pragma unroll
        for (int j = 0; j < 4; j++)
            #pragma unroll
            for (int e = 0; e < 4; e++) acc2[i][j][e] = 0.0f;

    #pragma unroll 1
    for (int nc = 0; nc < NC2; nc++) {
        cp_wait<1>();
        __syncthreads();
        const __half* bS = U + OFF_W2 + (nc % 3) * W2_BUFH;
        #pragma unroll
        for (int ks = 0; ks < 2; ks++) {
            uint32_t af[4][4], bf[4][2];
            #pragma unroll
            for (int mt = 0; mt < 4; mt++) {
                const __half* ap = hS + (wm * 64 + mt * 16 + ql) * HSTR_H
                                 + nc * 32 + ks * 16 + rl * 2;
                af[mt][0] = *(const uint32_t*)(ap);
                af[mt][1] = *(const uint32_t*)(ap + 8 * HSTR_H);
                af[mt][2] = *(const uint32_t*)(ap + 8);
                af[mt][3] = *(const uint32_t*)(ap + 8 * HSTR_H + 8);
            }
            #pragma unroll
            for (int nt = 0; nt < 4; nt++) {
                const __half* bp = bS + (wn * 32 + nt * 8 + ql) * SA_H + ks * 16 + rl * 2;
                bf[nt][0] = *(const uint32_t*)(bp);
                bf[nt][1] = *(const uint32_t*)(bp + 8);
            }
            #pragma unroll
            for (int mt = 0; mt < 4; mt++)
                #pragma unroll
                for (int nt = 0; nt < 4; nt++)
                    mma_f16(acc2[mt][nt], af[mt], bf[nt]);
        }
        ldW2(nc + 2);
    }

    // ---- phase-2 epilogue ----
    float* outB = out + (size_t)R0 * H2_;
    #pragma unroll
    for (int nt = 0; nt < 4; nt++) {
        const int cb = wn * 32 + nt * 8 + rl * 2;
        const float bx = sB2[cb], by = sB2[cb + 1];
        #pragma unroll
        for (int mt = 0; mt < 4; mt++) {
            const int r0 = wm * 64 + mt * 16 + ql;
            float v0 = fmaxf(acc2[mt][nt][0] + bx, 0.0f);
            float v1 = fmaxf(acc2[mt][nt][1] + by, 0.0f);
            float v2 = fmaxf(acc2[mt][nt][2] + bx, 0.0f);
            float v3 = fmaxf(acc2[mt][nt][3] + by, 0.0f);
            *(float2*)(outB + (size_t)r0 * H2_ + cb)       = make_float2(v0, v1);
            *(float2*)(outB + (size_t)(r0 + 8) * H2_ + cb) = make_float2(v2, v3);
        }
    }
}

// ---------------- launch ------------------------------------------------------
extern "C" void kernel_launch(void* const* d_in, const int* in_sizes, int n_in,
                              void* d_out, int out_size) {
    const float* xyz1    = (const float*)d_in[0];
    const float* xyz2    = (const float*)d_in[1];
    const float* points1 = (const float*)d_in[2];
    const float* points2 = (const float*)d_in[3];
    const float* W1      = (const float*)d_in[4];
    const float* b1      = (const float*)d_in[5];
    const float* W2      = (const float*)d_in[6];
    const float* b2      = (const float*)d_in[7];
    float* out = (float*)d_out;

    __half *gw1, *gw2;
    cudaGetSymbolAddress((void**)&gw1, g_W1t);
    cudaGetSymbolAddress((void**)&gw2, g_W2t);

    cudaFuncSetAttribute(fused_mlp,
                         cudaFuncAttributeMaxDynamicSharedMemorySize, SMEM_BYTES);

    // 1) weight transposes (half) + three_nn
    transpose_half<<<dim3(CIN_ / 32, H1_ / 32), dim3(32, 8)>>>(W1, gw1, CIN_, H1_);
    transpose_half<<<dim3(H1_ / 32, H2_ / 32), dim3(32, 8)>>>(W2, gw2, H1_, H2_);
    dim3 g1(N_ / 256, B_);
    knn3_kernel<<<g1, 256>>>(xyz1, xyz2);

    // 2) fused interp + MLP (512 CTAs of 128 points)
    fused_mlp<<<BNPTS / 128, 256, SMEM_BYTES>>>(points1, points2, b1, b2, out);
}